// round 14
// baseline (speedup 1.0000x reference)
#include <cuda_runtime.h>
#include <cstdint>
#include <math.h>

// bayes_55018531062578  (R14: 4-way interleaved threefry with IMAD.WIDE
//                        rotations — pipe balance + latency hiding combined)
//
// out[b] = sigmoid( BEVb[b]-BEVa[b] + (sum_{s<kapa} B[b,k*,s] - A[b,k*,s]) / kapa[b] )
// k*(b,s) = argmax_k ( log_softmax(mean)_k + gumbel(b,s,k) )
// gumbel: JAX partitionable threefry counter mode, bits = o0^o1 of
//   threefry2x32(key=(0,42), (0, i)),  u = bitcast((bits>>9)|0x3f800000)-1
// Fast argmax == argmax_k log2(u_k) * iw_k  (iw_k = 1/softmax_k, both neg/pos
// monotone-consistent); near-tie fallback replays reference formula in fp32.
//
// Round: x0 += x1;  x1 = rotl(x1,r) ^ x0
//   rotl via ONE mul.wide.u32 (IMAD.WIDE, fma pipe) then fused
//   LOP3(lo,hi,x0,0x56) = (lo|hi)^x0 (alu pipe). alu-mandatory work halves
//   (160 -> 80 instrs/sample); 4-way k-interleave hides the wide-op latency
//   that sank R12.

#define EPSF 1e-20f

// x1 = rotl(x1, r) ^ x0, with m = 1u<<r passed at runtime (no strength-reduce)
__device__ __forceinline__ uint32_t rotxor_wide(uint32_t x1, uint32_t m, uint32_t x0) {
    uint64_t w;
    asm("mul.wide.u32 %0, %1, %2;" : "=l"(w) : "r"(x1), "r"(m));
    const uint32_t lo = (uint32_t)w;
    const uint32_t hi = (uint32_t)(w >> 32);
    uint32_t res;
    asm("lop3.b32 %0, %1, %2, %3, 0x56;" : "=r"(res) : "r"(lo), "r"(hi), "r"(x0));
    return res;  // (lo | hi) ^ x0
}

struct RotM { uint32_t m13, m15, m26, m6, m17, m29, m16, m24, m23; };

// 4 interleaved threefry2x32 calls, key (0,42), inputs (0, c0+k), k=0..3.
__device__ __forceinline__ void threefry_xor4(uint32_t c0, const RotM r,
                                              uint32_t bits[4]) {
    const uint32_t ks0 = 0u;
    const uint32_t ks1 = 42u;
    const uint32_t ks2 = 0x1BD11BDAu ^ 42u;

    uint32_t x0[4], x1[4];
#pragma unroll
    for (int k = 0; k < 4; k++) { x0[k] = ks0; x1[k] = c0 + (uint32_t)k + ks1; }

#define TF_R(mm) _Pragma("unroll") \
    for (int k = 0; k < 4; k++) { x0[k] += x1[k]; x1[k] = rotxor_wide(x1[k], (mm), x0[k]); }
#define TF_INJ(i0, i1) _Pragma("unroll") \
    for (int k = 0; k < 4; k++) { x0[k] += (i0); x1[k] += (i1); }

    TF_R(r.m13) TF_R(r.m15) TF_R(r.m26) TF_R(r.m6)
    TF_INJ(ks1, ks2 + 1u)
    TF_R(r.m17) TF_R(r.m29) TF_R(r.m16) TF_R(r.m24)
    TF_INJ(ks2, ks0 + 2u)
    TF_R(r.m13) TF_R(r.m15) TF_R(r.m26) TF_R(r.m6)
    TF_INJ(ks0, ks1 + 3u)
    TF_R(r.m17) TF_R(r.m29) TF_R(r.m16) TF_R(r.m24)
    TF_INJ(ks1, ks2 + 4u)
    TF_R(r.m13) TF_R(r.m15) TF_R(r.m26) TF_R(r.m6)
    TF_INJ(ks2, ks0 + 5u)

#undef TF_R
#undef TF_INJ
#pragma unroll
    for (int k = 0; k < 4; k++) bits[k] = x0[k] ^ x1[k];
}

// u = bitcast((bits>>9)|0x3f800000) - 1 ; shift as mulhi (fma pipe), OR as
// carry-free add.
__device__ __forceinline__ float bits_to_uniform(uint32_t bits, uint32_t m23) {
    uint32_t hi;
    asm("mul.hi.u32 %0, %1, %2;" : "=r"(hi) : "r"(bits), "r"(m23));
    return __uint_as_float(hi + 0x3f800000u) - 1.0f;
}

__global__ __launch_bounds__(256, 6)
void bayes_kernel(const float* __restrict__ A,
                  const float* __restrict__ Bm,
                  const float* __restrict__ BEVa,
                  const float* __restrict__ BEVb,
                  const int*   __restrict__ kapa,
                  const float* __restrict__ mean,
                  float* __restrict__ out,
                  int S, RotM rm) {
    const int b    = blockIdx.x;
    const int tid  = threadIdx.x;
    const int warp = tid >> 5;
    const int lane = tid & 31;
    const int s    = tid;              // warp c covers s in [32c, 32c+32)

    __shared__ float red[8];

    const int kap = kapa[b];

    // Dead warp: publish zero partial, exit (exited threads skip the barrier).
    if ((warp << 5) >= kap) {
        if (lane == 0) red[warp] = 0.0f;
        return;
    }

    // inverse softmax weights (common denominator cancels in the arg-extreme)
    const float m0 = mean[0], m1 = mean[1], m2 = mean[2], m3 = mean[3];
    const float mx = fmaxf(fmaxf(m0, m1), fmaxf(m2, m3));
    const float e0 = __expf(m0 - mx), e1 = __expf(m1 - mx);
    const float e2 = __expf(m2 - mx), e3 = __expf(m3 - mx);
    const float iw[4] = {__fdividef(1.0f, e0), __fdividef(1.0f, e1),
                         __fdividef(1.0f, e2), __fdividef(1.0f, e3)};
    const float iwmax = fmaxf(fmaxf(iw[0], iw[1]), fmaxf(iw[2], iw[3]));

    float diff = 0.0f;

    if (s < kap) {
        const uint32_t base = ((uint32_t)b * (uint32_t)S + (uint32_t)s) * 4u;

        uint32_t bits[4];
        threefry_xor4(base, rm, bits);

        // q[k] = log2(u_k) * iw_k  (both <= 0); argmax == reference argmax.
        // u==0 -> log2f = -inf -> q = -inf, never selected (matches reference
        // where u=0 yields the weakest gumbel).
        float u[4], q[4];
#pragma unroll
        for (int k = 0; k < 4; k++) {
            u[k] = bits_to_uniform(bits[k], rm.m23);
            q[k] = __log2f(u[k]) * iw[k];
        }

        // argmax with runner-up tracking
        int   kb = 0;
        float best = q[0], second = -INFINITY;
        if (q[1] > best) { second = best; best = q[1]; kb = 1; } else second = q[1];
        if (q[2] > best) { second = best; best = q[2]; kb = 2; } else if (q[2] > second) second = q[2];
        if (q[3] > best) { second = best; best = q[3]; kb = 3; } else if (q[3] > second) second = q[3];

        // Error-model gate (~40x safety on log2f approx error)
        const float thresh = iwmax * 2e-5f + fabsf(second) * 1e-5f;
        if (best - second < thresh) {
            // rare accurate fp32 fallback: exact reference formula (with eps)
            const float se  = e0 + e1 + e2 + e3;
            const float lse = mx + logf(se);
            const float lg[4] = {m0 - lse, m1 - lse, m2 - lse, m3 - lse};
            float bs = -INFINITY; int kk = 0;
#pragma unroll
            for (int k = 0; k < 4; k++) {
                const float g  = -logf(-logf(u[k] + EPSF) + EPSF);
                const float sc = lg[k] + g;
                if (sc > bs) { bs = sc; kk = k; }
            }
            kb = kk;
        }

        const float* Ab = A  + (size_t)b * 4 * S;
        const float* Bb = Bm + (size_t)b * 4 * S;
        const size_t off = (size_t)kb * S + s;
        diff = Bb[off] - Ab[off];
    }

    // warp reduction
#pragma unroll
    for (int o = 16; o > 0; o >>= 1)
        diff += __shfl_down_sync(0xffffffffu, diff, o);
    if (lane == 0) red[warp] = diff;

    __syncthreads();

    if (tid == 0) {
        float tot = 0.0f;
#pragma unroll
        for (int wi = 0; wi < 8; wi++) tot += red[wi];
        const float x = BEVb[b] - BEVa[b] + tot / (float)kap;
        out[b] = 1.0f / (1.0f + expf(-x));
    }
}

extern "C" void kernel_launch(void* const* d_in, const int* in_sizes, int n_in,
                              void* d_out, int out_size) {
    // metadata order: outcomeA, outcomeB, BEVa, BEVb, kapa, batch_size, features, mean
    const float* A    = (const float*)d_in[0];
    const float* Bm   = (const float*)d_in[1];
    const float* BEVa = (const float*)d_in[2];
    const float* BEVb = (const float*)d_in[3];
    const int*   kapa = (const int*)  d_in[4];

    // mean is the (only) 4-element input; locate it robustly from the tail
    const float* mean = (const float*)d_in[n_in - 1];
    for (int i = n_in - 1; i >= 5; --i) {
        if (in_sizes[i] == 4) { mean = (const float*)d_in[i]; break; }
    }

    float* out = (float*)d_out;

    const int B = in_sizes[2];                 // 16384
    const int S = in_sizes[0] / (4 * B);       // 256

    RotM rm;
    rm.m13 = 1u << 13; rm.m15 = 1u << 15; rm.m26 = 1u << 26; rm.m6  = 1u << 6;
    rm.m17 = 1u << 17; rm.m29 = 1u << 29; rm.m16 = 1u << 16; rm.m24 = 1u << 24;
    rm.m23 = 1u << 23;

    bayes_kernel<<<B, 256>>>(A, Bm, BEVa, BEVb, kapa, mean, out, S, rm);
}

// round 15
// speedup vs baseline: 1.2355x; 1.2355x over previous
#include <cuda_runtime.h>
#include <cstdint>
#include <math.h>

// bayes_55018531062578  (R15: 128-thread block per b, 2 sample-slots per warp,
//                        4-way interleaved threefry per slot)
//
// out[b] = sigmoid( BEVb[b]-BEVa[b] + (sum_{s<kapa} B[b,k*,s] - A[b,k*,s]) / kapa[b] )
// k*(b,s) = argmax_k ( log_softmax(mean)_k + gumbel(b,s,k) )
// gumbel: JAX partitionable threefry counter mode, bits = o0^o1 of
//   threefry2x32(key=(0,42), (0, i)),  u = bitcast((bits>>9)|0x3f800000)-1
// Fast argmax == argmin_k t_k * (1/w_k),  t_k = -log2(u_k); near-tie
// fallback (rate ~1e-4) replays reference formula (with eps) in fp32.
//
// Warp w covers s in {32w+lane, 128+32w+lane}: prologue (mean loads, 7 MUFU,
// kapa stall) amortized over up to 64 samples; slot efficiency ~75% vs 56%
// for the 8-warp/1-slot layout; both slots unrolled -> up to 8 independent
// threefry chains in flight.

#define EPSF 1e-20f

__device__ __forceinline__ uint32_t rotl32(uint32_t x, int r) {
    return __funnelshift_l(x, x, r);
}

// 4 interleaved threefry2x32 calls, key (0,42), inputs (0, c0+k), k=0..3.
__device__ __forceinline__ void threefry_xor4(uint32_t c0, uint32_t bits[4]) {
    const uint32_t ks0 = 0u;
    const uint32_t ks1 = 42u;
    const uint32_t ks2 = 0x1BD11BDAu ^ 42u;

    uint32_t x0[4], x1[4];
#pragma unroll
    for (int k = 0; k < 4; k++) { x0[k] = ks0; x1[k] = c0 + (uint32_t)k + ks1; }

#define TF_R(r) _Pragma("unroll") \
    for (int k = 0; k < 4; k++) { x0[k] += x1[k]; x1[k] = rotl32(x1[k],(r)) ^ x0[k]; }
#define TF_INJ(i0, i1) _Pragma("unroll") \
    for (int k = 0; k < 4; k++) { x0[k] += (i0); x1[k] += (i1); }

    TF_R(13) TF_R(15) TF_R(26) TF_R(6)
    TF_INJ(ks1, ks2 + 1u)
    TF_R(17) TF_R(29) TF_R(16) TF_R(24)
    TF_INJ(ks2, ks0 + 2u)
    TF_R(13) TF_R(15) TF_R(26) TF_R(6)
    TF_INJ(ks0, ks1 + 3u)
    TF_R(17) TF_R(29) TF_R(16) TF_R(24)
    TF_INJ(ks1, ks2 + 4u)
    TF_R(13) TF_R(15) TF_R(26) TF_R(6)
    TF_INJ(ks2, ks0 + 5u)

#undef TF_R
#undef TF_INJ
#pragma unroll
    for (int k = 0; k < 4; k++) bits[k] = x0[k] ^ x1[k];
}

__device__ __forceinline__ float bits_to_uniform(uint32_t bits) {
    return __uint_as_float((bits >> 9) | 0x3f800000u) - 1.0f;
}

__global__ __launch_bounds__(128, 10)
void bayes_kernel(const float* __restrict__ A,
                  const float* __restrict__ Bm,
                  const float* __restrict__ BEVa,
                  const float* __restrict__ BEVb,
                  const int*   __restrict__ kapa,
                  const float* __restrict__ mean,
                  float* __restrict__ out,
                  int S) {
    const int b    = blockIdx.x;
    const int tid  = threadIdx.x;
    const int warp = tid >> 5;       // 0..3
    const int lane = tid & 31;

    __shared__ float red[4];

    const int kap = kapa[b];

    // Warp fully dead iff even its first slot's chunk start >= kap.
    if ((warp << 5) >= kap) {
        if (lane == 0) red[warp] = 0.0f;
        return;
    }

    // Prologue (amortized over up to 64 samples): inverse softmax weights.
    const float m0 = mean[0], m1 = mean[1], m2 = mean[2], m3 = mean[3];
    const float mx = fmaxf(fmaxf(m0, m1), fmaxf(m2, m3));
    const float e0 = __expf(m0 - mx), e1 = __expf(m1 - mx);
    const float e2 = __expf(m2 - mx), e3 = __expf(m3 - mx);
    const float iw[4] = {__fdividef(1.0f, e0), __fdividef(1.0f, e1),
                         __fdividef(1.0f, e2), __fdividef(1.0f, e3)};
    const float iwmax = fmaxf(fmaxf(iw[0], iw[1]), fmaxf(iw[2], iw[3]));

    const float* Ab = A  + (size_t)b * 4 * S;
    const float* Bb = Bm + (size_t)b * 4 * S;

    float diff = 0.0f;

#pragma unroll
    for (int slot = 0; slot < 2; slot++) {
        const int s = slot * 128 + (warp << 5) + lane;
        // whole-warp predicate (uniform within warp): chunk start < kap
        if (slot * 128 + (warp << 5) < kap) {
            const uint32_t base = ((uint32_t)b * (uint32_t)S + (uint32_t)s) * 4u;

            uint32_t bits[4];
            threefry_xor4(base, bits);

            float u[4], q[4];
#pragma unroll
            for (int k = 0; k < 4; k++) {
                u[k] = bits_to_uniform(bits[k]);
                const float t = -__log2f(u[k]);   // u==0 -> +inf, never wins
                q[k] = t * iw[k];
            }

            // argmin with runner-up tracking
            int   kb = 0;
            float best = q[0], second = INFINITY;
            if (q[1] < best) { second = best; best = q[1]; kb = 1; } else second = q[1];
            if (q[2] < best) { second = best; best = q[2]; kb = 2; } else if (q[2] < second) second = q[2];
            if (q[3] < best) { second = best; best = q[3]; kb = 3; } else if (q[3] < second) second = q[3];

            // Error-model gate (~40x safety on fast-path fp error)
            const float thresh = iwmax * 2e-5f + second * 1e-5f;
            if (second - best < thresh) {
                // rare accurate fp32 fallback: exact reference formula
                const float se  = e0 + e1 + e2 + e3;
                const float lse = mx + logf(se);
                const float lg[4] = {m0 - lse, m1 - lse, m2 - lse, m3 - lse};
                float bs = -INFINITY; int kk = 0;
#pragma unroll
                for (int k = 0; k < 4; k++) {
                    const float g  = -logf(-logf(u[k] + EPSF) + EPSF);
                    const float sc = lg[k] + g;
                    if (sc > bs) { bs = sc; kk = k; }
                }
                kb = kk;
            }

            if (s < kap) {
                const size_t off = (size_t)kb * S + s;
                diff += Bb[off] - Ab[off];
            }
        }
    }

    // warp reduction
#pragma unroll
    for (int o = 16; o > 0; o >>= 1)
        diff += __shfl_down_sync(0xffffffffu, diff, o);
    if (lane == 0) red[warp] = diff;

    __syncthreads();

    if (tid == 0) {
        const float tot = red[0] + red[1] + red[2] + red[3];
        const float x = BEVb[b] - BEVa[b] + tot / (float)kap;
        out[b] = 1.0f / (1.0f + expf(-x));
    }
}

extern "C" void kernel_launch(void* const* d_in, const int* in_sizes, int n_in,
                              void* d_out, int out_size) {
    // metadata order: outcomeA, outcomeB, BEVa, BEVb, kapa, batch_size, features, mean
    const float* A    = (const float*)d_in[0];
    const float* Bm   = (const float*)d_in[1];
    const float* BEVa = (const float*)d_in[2];
    const float* BEVb = (const float*)d_in[3];
    const int*   kapa = (const int*)  d_in[4];

    // mean is the (only) 4-element input; locate it robustly from the tail
    const float* mean = (const float*)d_in[n_in - 1];
    for (int i = n_in - 1; i >= 5; --i) {
        if (in_sizes[i] == 4) { mean = (const float*)d_in[i]; break; }
    }

    float* out = (float*)d_out;

    const int B = in_sizes[2];                 // 16384
    const int S = in_sizes[0] / (4 * B);       // 256

    bayes_kernel<<<B, 128>>>(A, Bm, BEVa, BEVb, kapa, mean, out, S);
}